// round 7
// baseline (speedup 1.0000x reference)
#include <cuda_runtime.h>

#define BB 64
#define NP 1024
#define LL 64
#define HH 128
#define W1K 67            // 3 + L (W1 row length)
#define ROW 132           // padded smem row for o-dim (floats)
#define HROW 68           // padded smem row for h/x tiles (64 + 4)
#define TN2 64            // points per MLP tile
#define NTILES (BB * 16)  // 1024 tiles of 64 points
#define MLP_GRID 148

__device__ float g_acc[3];        // [0]=chamfer dir0, [1]=dir1, [2]=l2
__device__ float g_w1l[BB * HH];  // per-batch latent part of layer 1 + b1

__global__ void init_kernel() {
    if (threadIdx.x < 3) g_acc[threadIdx.x] = 0.0f;
}

// W1L[b][o] = b1[o] + sum_l W1[o][3+l] * latent[b][l]
__global__ void __launch_bounds__(128) w1l_kernel(
    const float* __restrict__ latent, const float* __restrict__ W1,
    const float* __restrict__ b1)
{
    __shared__ float slat[LL];
    const int b = blockIdx.x, o = threadIdx.x;
    if (o < LL) slat[o] = latent[b * LL + o];
    __syncthreads();
    float acc = b1[o];
    const float* wrow = W1 + o * W1K + 3;
    #pragma unroll 8
    for (int l = 0; l < LL; l++) acc = fmaf(wrow[l], slat[l], acc);
    g_w1l[b * HH + o] = acc;
}

__device__ __forceinline__ float block_sum(float v, float* scratch) {
    #pragma unroll
    for (int off = 16; off; off >>= 1) v += __shfl_down_sync(0xffffffffu, v, off);
    int lane = threadIdx.x & 31, w = threadIdx.x >> 5;
    if (lane == 0) scratch[w] = v;
    __syncthreads();
    int nw = blockDim.x >> 5;
    v = (threadIdx.x < nw) ? scratch[threadIdx.x] : 0.0f;
    if (w == 0) {
        #pragma unroll
        for (int off = 16; off; off >>= 1) v += __shfl_down_sync(0xffffffffu, v, off);
    }
    return v;  // valid on thread 0
}

// ---------------------------------------------------------------------------
// Persistent MLP: 148 CTAs, each loops over 1024 tiles of 64 points.
// Weights staged once per CTA; per tile: h1 = relu(W1pc@pc + W1L[b]);
// h2 = relu(W2@h1 + b2); noise = W3@h2 + b3; pc_est = pc - noise; L2 partial
// kept in a register across tiles.
// ---------------------------------------------------------------------------
__global__ void __launch_bounds__(256) mlp_kernel(
    const float* __restrict__ pc, const float* __restrict__ pc_gt,
    const float* __restrict__ W1,
    const float* __restrict__ W2, const float* __restrict__ b2,
    const float* __restrict__ W3, const float* __restrict__ b3,
    float* __restrict__ out_est)
{
    extern __shared__ float sm[];
    float* s_w2 = sm;                    // [HH][ROW]   W2^T: [k][o]
    float* s_h  = sm + HH * ROW;         // [HH][HROW]  h1 then h2, [k][n]
    float* s_wx = s_h + HH * HROW;       // [3][ROW]    W1 pc-part, [k][o]
    float* s_x  = s_wx + 3 * ROW;        // [3][HROW]   pc tile, [k][n]
    float* swl  = s_x + 3 * HROW;        // 128 : W1L row for current batch
    float* sb2  = swl + 128;             // 128
    float* sw3  = sb2 + 128;             // 384
    float* sb3  = sw3 + 384;             // 4
    float* sred = sb3 + 4;               // 8

    const int tid = threadIdx.x;

    // ---- one-time stage: W2^T, W1 pc-columns, b2, W3, b3 ----
    for (int i = tid; i < HH * HH; i += 256) {
        int o = i >> 7, k = i & 127;
        s_w2[k * ROW + o] = W2[i];
    }
    if (tid < 128) {
        s_wx[0 * ROW + tid] = W1[tid * W1K + 0];
        s_wx[1 * ROW + tid] = W1[tid * W1K + 1];
        s_wx[2 * ROW + tid] = W1[tid * W1K + 2];
        sb2[tid] = b2[tid];
    }
    for (int i = tid; i < 384; i += 256) sw3[i] = W3[i];
    if (tid < 3) sb3[tid] = b3[tid];

    const int to = (tid >> 3) * 4;   // 32 groups x 4 -> 128 outputs
    const int tn = (tid & 7) * 8;    // 8 groups x 8  -> 64 points
    const int l3r = tid & 3;         // layer-3 output row (0..2 active)
    const int l3n = tid >> 2;        // layer-3 point (0..63)

    float l2acc = 0.0f;

    for (int t = blockIdx.x; t < NTILES; t += MLP_GRID) {
        const int b  = t >> 4;
        const int n0 = (t & 15) * TN2;

        __syncthreads();   // prior tile's layer-3 reads of s_h done
        // ---- stage pc tile + W1L row ----
        for (int i = tid; i < 3 * TN2; i += 256) {
            int k = i >> 6, n = i & 63;
            s_x[k * HROW + n] = pc[(b * 3 + k) * NP + n0 + n];
        }
        if (tid < 128) swl[tid] = g_w1l[b * HH + tid];
        __syncthreads();

        float acc[4][8];
        #pragma unroll
        for (int i = 0; i < 4; i++)
            #pragma unroll
            for (int j = 0; j < 8; j++) acc[i][j] = 0.0f;

        // ---- layer 1: 3-deep ----
        #pragma unroll
        for (int k = 0; k < 3; k++) {
            float4 a0 = *(const float4*)&s_wx[k * ROW + to];
            float4 c0 = *(const float4*)&s_x[k * HROW + tn];
            float4 c1 = *(const float4*)&s_x[k * HROW + tn + 4];
            float a[4] = {a0.x, a0.y, a0.z, a0.w};
            float c[8] = {c0.x, c0.y, c0.z, c0.w, c1.x, c1.y, c1.z, c1.w};
            #pragma unroll
            for (int i = 0; i < 4; i++)
                #pragma unroll
                for (int j = 0; j < 8; j++) acc[i][j] = fmaf(a[i], c[j], acc[i][j]);
        }
        #pragma unroll
        for (int i = 0; i < 4; i++) {
            float bi = swl[to + i];
            #pragma unroll
            for (int j = 0; j < 8; j++)
                s_h[(to + i) * HROW + tn + j] = fmaxf(acc[i][j] + bi, 0.0f);
        }
        __syncthreads();

        #pragma unroll
        for (int i = 0; i < 4; i++)
            #pragma unroll
            for (int j = 0; j < 8; j++) acc[i][j] = 0.0f;

        // ---- layer 2: 128x64x128 ----
        #pragma unroll 2
        for (int k = 0; k < HH; k++) {
            float4 a0 = *(const float4*)&s_w2[k * ROW + to];
            float4 c0 = *(const float4*)&s_h[k * HROW + tn];
            float4 c1 = *(const float4*)&s_h[k * HROW + tn + 4];
            float a[4] = {a0.x, a0.y, a0.z, a0.w};
            float c[8] = {c0.x, c0.y, c0.z, c0.w, c1.x, c1.y, c1.z, c1.w};
            #pragma unroll
            for (int i = 0; i < 4; i++)
                #pragma unroll
                for (int j = 0; j < 8; j++) acc[i][j] = fmaf(a[i], c[j], acc[i][j]);
        }
        __syncthreads();   // all h1 reads done; overwrite s_h with h2
        #pragma unroll
        for (int i = 0; i < 4; i++) {
            float bi = sb2[to + i];
            #pragma unroll
            for (int j = 0; j < 8; j++)
                s_h[(to + i) * HROW + tn + j] = fmaxf(acc[i][j] + bi, 0.0f);
        }
        __syncthreads();

        // ---- layer 3 (3x128) + epilogue ----
        if (l3r < 3) {
            float o0 = sb3[l3r];
            const float* w3r = sw3 + l3r * HH;
            #pragma unroll 4
            for (int k = 0; k < HH; k++)
                o0 = fmaf(w3r[k], s_h[k * HROW + l3n], o0);
            int idx = (b * 3 + l3r) * NP + n0 + l3n;
            float e = pc[idx] - o0;
            out_est[idx] = e;
            float d = pc_gt[idx] - e;
            l2acc = fmaf(d, d, l2acc);
        }
    }

    __syncthreads();
    float s = block_sum(l2acc, sred);
    if (tid == 0) atomicAdd(&g_acc[2], s);
}

// ---------------------------------------------------------------------------
// Chamfer via d = a^2 + b^2 - 2*dot. Each THREAD carries 4 query points so
// every spts[m] LDS.128 is amortized over 4 dot products.
// grid = (64 batches, 2 directions), 256 threads.
// ---------------------------------------------------------------------------
__global__ void __launch_bounds__(256) chamfer_kernel(
    const float* __restrict__ pc_gt, const float* __restrict__ est)
{
    __shared__ float4 spts[NP];
    __shared__ float sred[8];
    const int b = blockIdx.x;
    const int dir = blockIdx.y;
    const float* rows  = dir ? est   : pc_gt;
    const float* other = dir ? pc_gt : est;
    const int base = b * 3 * NP;

    for (int i = threadIdx.x; i < NP; i += 256) {
        float x = other[base + i];
        float y = other[base + NP + i];
        float z = other[base + 2 * NP + i];
        spts[i] = make_float4(x, y, z, fmaf(x, x, fmaf(y, y, z * z)));
    }
    __syncthreads();

    float qx[4], qy[4], qz[4], qa2[4];
    #pragma unroll
    for (int q = 0; q < 4; q++) {
        int n = threadIdx.x + q * 256;
        float ax = rows[base + n];
        float ay = rows[base + NP + n];
        float az = rows[base + 2 * NP + n];
        qa2[q] = fmaf(ax, ax, fmaf(ay, ay, az * az));
        qx[q] = -2.0f * ax;
        qy[q] = -2.0f * ay;
        qz[q] = -2.0f * az;
    }

    float bst[4][2];
    #pragma unroll
    for (int q = 0; q < 4; q++) { bst[q][0] = 3.4e38f; bst[q][1] = 3.4e38f; }

    for (int m = 0; m < NP; m += 4) {
        float4 p0 = spts[m];
        float4 p1 = spts[m + 1];
        float4 p2 = spts[m + 2];
        float4 p3 = spts[m + 3];
        #pragma unroll
        for (int q = 0; q < 4; q++) {
            float t0 = fmaf(qz[q], p0.z, fmaf(qy[q], p0.y, fmaf(qx[q], p0.x, p0.w)));
            float t1 = fmaf(qz[q], p1.z, fmaf(qy[q], p1.y, fmaf(qx[q], p1.x, p1.w)));
            float t2 = fmaf(qz[q], p2.z, fmaf(qy[q], p2.y, fmaf(qx[q], p2.x, p2.w)));
            float t3 = fmaf(qz[q], p3.z, fmaf(qy[q], p3.y, fmaf(qx[q], p3.x, p3.w)));
            bst[q][0] = fminf(bst[q][0], fminf(t0, t1));
            bst[q][1] = fminf(bst[q][1], fminf(t2, t3));
        }
    }

    float acc = 0.0f;
    #pragma unroll
    for (int q = 0; q < 4; q++)
        acc += qa2[q] + fminf(bst[q][0], bst[q][1]);
    float s = block_sum(acc, sred);
    if (threadIdx.x == 0) atomicAdd(&g_acc[dir], s);
}

__global__ void final_kernel(float* __restrict__ out) {
    float ch = (g_acc[0] + g_acc[1]) * (1.0f / (float)(BB * NP));
    float l2 = g_acc[2] * (1.0f / (float)(BB * 3 * NP));
    out[0] = 0.1f * ch + 0.9f * l2;
    out[1] = ch;
    out[2] = l2;
}

extern "C" void kernel_launch(void* const* d_in, const int* in_sizes, int n_in,
                              void* d_out, int out_size) {
    const float* pc    = (const float*)d_in[0];
    const float* pc_gt = (const float*)d_in[1];
    const float* lat   = (const float*)d_in[2];
    const float* W1    = (const float*)d_in[3];
    const float* b1    = (const float*)d_in[4];
    const float* W2    = (const float*)d_in[5];
    const float* b2    = (const float*)d_in[6];
    const float* W3    = (const float*)d_in[7];
    const float* b3    = (const float*)d_in[8];
    float* out = (float*)d_out;

    size_t smem = (size_t)(HH * ROW + HH * HROW + 3 * ROW + 3 * HROW + 652)
                  * sizeof(float);
    (void)cudaFuncSetAttribute(mlp_kernel,
                               cudaFuncAttributeMaxDynamicSharedMemorySize,
                               (int)smem);

    init_kernel<<<1, 32>>>();
    w1l_kernel<<<BB, 128>>>(lat, W1, b1);
    mlp_kernel<<<MLP_GRID, 256, smem>>>(pc, pc_gt, W1, W2, b2, W3, b3, out + 3);
    chamfer_kernel<<<dim3(BB, 2), 256>>>(pc_gt, out + 3);
    final_kernel<<<1, 1>>>(out);
}

// round 8
// speedup vs baseline: 1.3075x; 1.3075x over previous
#include <cuda_runtime.h>

#define BB 64
#define NP 1024
#define LL 64
#define HH 128
#define W1K 67           // 3 + L (W1 row length)
#define ROW 132          // padded smem row (floats)
#define TN 128           // points per MLP tile
#define NT (BB * 8)      // 512 tiles of 128 points
#define MLP_GRID 148

__device__ float g_acc[3];        // [0]=chamfer dir0, [1]=dir1, [2]=l2
__device__ float g_w1l[BB * HH];  // per-batch latent part of layer 1 + b1

__global__ void init_kernel() {
    if (threadIdx.x < 3) g_acc[threadIdx.x] = 0.0f;
}

// W1L[b][o] = b1[o] + sum_l W1[o][3+l] * latent[b][l]
__global__ void __launch_bounds__(128) w1l_kernel(
    const float* __restrict__ latent, const float* __restrict__ W1,
    const float* __restrict__ b1)
{
    __shared__ float slat[LL];
    const int b = blockIdx.x, o = threadIdx.x;
    if (o < LL) slat[o] = latent[b * LL + o];
    __syncthreads();
    float acc = b1[o];
    const float* wrow = W1 + o * W1K + 3;
    #pragma unroll 8
    for (int l = 0; l < LL; l++) acc = fmaf(wrow[l], slat[l], acc);
    g_w1l[b * HH + o] = acc;
}

__device__ __forceinline__ float block_sum(float v, float* scratch) {
    #pragma unroll
    for (int off = 16; off; off >>= 1) v += __shfl_down_sync(0xffffffffu, v, off);
    int lane = threadIdx.x & 31, w = threadIdx.x >> 5;
    if (lane == 0) scratch[w] = v;
    __syncthreads();
    int nw = blockDim.x >> 5;
    v = (threadIdx.x < nw) ? scratch[threadIdx.x] : 0.0f;
    if (w == 0) {
        #pragma unroll
        for (int off = 16; off; off >>= 1) v += __shfl_down_sync(0xffffffffu, v, off);
    }
    return v;  // valid on thread 0
}

// ---------------------------------------------------------------------------
// Persistent MLP with the R5 tile: 148 CTAs loop over 512 tiles of 128 pts.
// Inner loops identical to the proven R5 kernel (8x8 microtiles, 256 thr);
// W2^T/W1pc/b2/W3/b3 staged into SMEM once per CTA.
// ---------------------------------------------------------------------------
__global__ void __launch_bounds__(256) mlp_kernel(
    const float* __restrict__ pc, const float* __restrict__ pc_gt,
    const float* __restrict__ W1,
    const float* __restrict__ W2, const float* __restrict__ b2,
    const float* __restrict__ W3, const float* __restrict__ b3,
    float* __restrict__ out_est)
{
    extern __shared__ float sm[];
    float* s_w2 = sm;                    // [HH][ROW]  W2^T: [k][o]
    float* s_h  = sm + HH * ROW;         // [HH][ROW]  h1 then h2, [k][n]
    float* s_wx = s_h + HH * ROW;        // [3][ROW]   W1 pc-part, [k][o]
    float* s_x  = s_wx + 3 * ROW;        // [3][ROW]   pc tile, [k][n]
    float* s_e  = s_x + 3 * ROW;
    float* swl  = s_e;            // 128 : W1L row for current batch
    float* sb2  = s_e + 128;      // 128
    float* sw3  = s_e + 256;      // 384
    float* sb3  = s_e + 640;      // 4
    float* sred = s_e + 644;      // 32

    const int tid = threadIdx.x;

    // ---- one-time stage: W2^T, W1 pc-columns, b2, W3, b3 ----
    for (int i = tid; i < HH * HH; i += 256) {
        int o = i >> 7, k = i & 127;
        s_w2[k * ROW + o] = W2[i];
    }
    if (tid < 128) {
        s_wx[0 * ROW + tid] = W1[tid * W1K + 0];
        s_wx[1 * ROW + tid] = W1[tid * W1K + 1];
        s_wx[2 * ROW + tid] = W1[tid * W1K + 2];
        sb2[tid] = b2[tid];
    }
    for (int i = tid; i < 384; i += 256) sw3[i] = W3[i];
    if (tid < 3) sb3[tid] = b3[tid];

    const int tn = (tid & 15) * 8;
    const int to = (tid >> 4) * 8;

    float l2acc = 0.0f;

    for (int t = blockIdx.x; t < NT; t += MLP_GRID) {
        const int b  = t >> 3;
        const int n0 = (t & 7) * TN;

        __syncthreads();   // prior tile's layer-3 / swl readers done
        for (int i = tid; i < 3 * TN; i += 256) {
            int k = i >> 7, n = i & 127;
            s_x[k * ROW + n] = pc[(b * 3 + k) * NP + n0 + n];
        }
        if (tid < 128) swl[tid] = g_w1l[b * HH + tid];
        __syncthreads();

        float acc[8][8];
        #pragma unroll
        for (int i = 0; i < 8; i++)
            #pragma unroll
            for (int j = 0; j < 8; j++) acc[i][j] = 0.0f;

        // ---- layer 1: 3-deep GEMM + precomputed latent term ----
        #pragma unroll
        for (int k = 0; k < 3; k++) {
            float4 a0 = *(const float4*)&s_wx[k * ROW + to];
            float4 a1 = *(const float4*)&s_wx[k * ROW + to + 4];
            float4 c0 = *(const float4*)&s_x[k * ROW + tn];
            float4 c1 = *(const float4*)&s_x[k * ROW + tn + 4];
            float a[8] = {a0.x, a0.y, a0.z, a0.w, a1.x, a1.y, a1.z, a1.w};
            float c[8] = {c0.x, c0.y, c0.z, c0.w, c1.x, c1.y, c1.z, c1.w};
            #pragma unroll
            for (int i = 0; i < 8; i++)
                #pragma unroll
                for (int j = 0; j < 8; j++) acc[i][j] = fmaf(a[i], c[j], acc[i][j]);
        }
        #pragma unroll
        for (int i = 0; i < 8; i++) {
            float bi = swl[to + i];
            #pragma unroll
            for (int j = 0; j < 8; j++)
                s_h[(to + i) * ROW + tn + j] = fmaxf(acc[i][j] + bi, 0.0f);
        }
        __syncthreads();

        #pragma unroll
        for (int i = 0; i < 8; i++)
            #pragma unroll
            for (int j = 0; j < 8; j++) acc[i][j] = 0.0f;

        // ---- layer 2: 128x128x128 GEMM (R5 mainloop) ----
        for (int k = 0; k < HH; k++) {
            float4 a0 = *(const float4*)&s_w2[k * ROW + to];
            float4 a1 = *(const float4*)&s_w2[k * ROW + to + 4];
            float4 c0 = *(const float4*)&s_h[k * ROW + tn];
            float4 c1 = *(const float4*)&s_h[k * ROW + tn + 4];
            float a[8] = {a0.x, a0.y, a0.z, a0.w, a1.x, a1.y, a1.z, a1.w};
            float c[8] = {c0.x, c0.y, c0.z, c0.w, c1.x, c1.y, c1.z, c1.w};
            #pragma unroll
            for (int i = 0; i < 8; i++)
                #pragma unroll
                for (int j = 0; j < 8; j++) acc[i][j] = fmaf(a[i], c[j], acc[i][j]);
        }
        __syncthreads();   // all h1 reads done; overwrite s_h with h2
        #pragma unroll
        for (int i = 0; i < 8; i++) {
            float bi = sb2[to + i];
            #pragma unroll
            for (int j = 0; j < 8; j++)
                s_h[(to + i) * ROW + tn + j] = fmaxf(acc[i][j] + bi, 0.0f);
        }
        __syncthreads();

        // ---- layer 3 (3x128) + epilogue: pc_est + L2 partial ----
        if (tid < TN) {
            int n = tid, g = n0 + n;
            float o0 = sb3[0], o1 = sb3[1], o2 = sb3[2];
            #pragma unroll 4
            for (int k = 0; k < HH; k++) {
                float hv = s_h[k * ROW + n];
                o0 = fmaf(sw3[k], hv, o0);
                o1 = fmaf(sw3[128 + k], hv, o1);
                o2 = fmaf(sw3[256 + k], hv, o2);
            }
            int base = (b * 3) * NP + g;
            float e0 = pc[base] - o0;
            float e1 = pc[base + NP] - o1;
            float e2 = pc[base + 2 * NP] - o2;
            out_est[base] = e0;
            out_est[base + NP] = e1;
            out_est[base + 2 * NP] = e2;
            float d0 = pc_gt[base] - e0;
            float d1 = pc_gt[base + NP] - e1;
            float d2 = pc_gt[base + 2 * NP] - e2;
            l2acc += fmaf(d0, d0, fmaf(d1, d1, d2 * d2));
        }
    }

    __syncthreads();
    float s = block_sum(l2acc, sred);
    if (tid == 0) atomicAdd(&g_acc[2], s);
}

// ---------------------------------------------------------------------------
// Chamfer: 512 threads/CTA. Threads keep the 4-query reuse (LDS amortized
// over 4 dots) but split the 1024-point scan in half across thread halves;
// partial mins combined via SMEM. 16 warps/SM hides LDS->FMA latency.
// grid = (64 batches, 2 directions).
// ---------------------------------------------------------------------------
__global__ void __launch_bounds__(512) chamfer_kernel(
    const float* __restrict__ pc_gt, const float* __restrict__ est)
{
    __shared__ float4 spts[NP];
    __shared__ float sup[256][4];
    __shared__ float sred[16];
    const int b = blockIdx.x;
    const int dir = blockIdx.y;
    const float* rows  = dir ? est   : pc_gt;
    const float* other = dir ? pc_gt : est;
    const int base = b * 3 * NP;
    const int tid  = threadIdx.x;
    const int qt   = tid & 255;
    const int half = tid >> 8;

    for (int i = tid; i < NP; i += 512) {
        float x = other[base + i];
        float y = other[base + NP + i];
        float z = other[base + 2 * NP + i];
        spts[i] = make_float4(x, y, z, fmaf(x, x, fmaf(y, y, z * z)));
    }
    __syncthreads();

    float qx[4], qy[4], qz[4], qa2[4];
    #pragma unroll
    for (int q = 0; q < 4; q++) {
        int n = qt + q * 256;
        float ax = rows[base + n];
        float ay = rows[base + NP + n];
        float az = rows[base + 2 * NP + n];
        qa2[q] = fmaf(ax, ax, fmaf(ay, ay, az * az));
        qx[q] = -2.0f * ax;
        qy[q] = -2.0f * ay;
        qz[q] = -2.0f * az;
    }

    float bst[4][2];
    #pragma unroll
    for (int q = 0; q < 4; q++) { bst[q][0] = 3.4e38f; bst[q][1] = 3.4e38f; }

    const int m0 = half * 512;
    for (int m = m0; m < m0 + 512; m += 4) {
        float4 p0 = spts[m];
        float4 p1 = spts[m + 1];
        float4 p2 = spts[m + 2];
        float4 p3 = spts[m + 3];
        #pragma unroll
        for (int q = 0; q < 4; q++) {
            float t0 = fmaf(qz[q], p0.z, fmaf(qy[q], p0.y, fmaf(qx[q], p0.x, p0.w)));
            float t1 = fmaf(qz[q], p1.z, fmaf(qy[q], p1.y, fmaf(qx[q], p1.x, p1.w)));
            float t2 = fmaf(qz[q], p2.z, fmaf(qy[q], p2.y, fmaf(qx[q], p2.x, p2.w)));
            float t3 = fmaf(qz[q], p3.z, fmaf(qy[q], p3.y, fmaf(qx[q], p3.x, p3.w)));
            bst[q][0] = fminf(bst[q][0], fminf(t0, t1));
            bst[q][1] = fminf(bst[q][1], fminf(t2, t3));
        }
    }

    if (half) {
        #pragma unroll
        for (int q = 0; q < 4; q++)
            sup[qt][q] = fminf(bst[q][0], bst[q][1]);
    }
    __syncthreads();

    float acc = 0.0f;
    if (!half) {
        #pragma unroll
        for (int q = 0; q < 4; q++) {
            float lo = fminf(bst[q][0], bst[q][1]);
            acc += qa2[q] + fminf(lo, sup[qt][q]);
        }
    }
    float s = block_sum(acc, sred);
    if (tid == 0) atomicAdd(&g_acc[dir], s);
}

__global__ void final_kernel(float* __restrict__ out) {
    float ch = (g_acc[0] + g_acc[1]) * (1.0f / (float)(BB * NP));
    float l2 = g_acc[2] * (1.0f / (float)(BB * 3 * NP));
    out[0] = 0.1f * ch + 0.9f * l2;
    out[1] = ch;
    out[2] = l2;
}

extern "C" void kernel_launch(void* const* d_in, const int* in_sizes, int n_in,
                              void* d_out, int out_size) {
    const float* pc    = (const float*)d_in[0];
    const float* pc_gt = (const float*)d_in[1];
    const float* lat   = (const float*)d_in[2];
    const float* W1    = (const float*)d_in[3];
    const float* b1    = (const float*)d_in[4];
    const float* W2    = (const float*)d_in[5];
    const float* b2    = (const float*)d_in[6];
    const float* W3    = (const float*)d_in[7];
    const float* b3    = (const float*)d_in[8];
    float* out = (float*)d_out;

    size_t smem = (size_t)(2 * HH * ROW + 6 * ROW + 676) * sizeof(float);
    (void)cudaFuncSetAttribute(mlp_kernel,
                               cudaFuncAttributeMaxDynamicSharedMemorySize,
                               (int)smem);

    init_kernel<<<1, 32>>>();
    w1l_kernel<<<BB, 128>>>(lat, W1, b1);
    mlp_kernel<<<MLP_GRID, 256, smem>>>(pc, pc_gt, W1, W2, b2, W3, b3, out + 3);
    chamfer_kernel<<<dim3(BB, 2), 512>>>(pc_gt, out + 3);
    final_kernel<<<1, 1>>>(out);
}

// round 11
// speedup vs baseline: 1.6743x; 1.2805x over previous
#include <cuda_runtime.h>
#include <cuda_bf16.h>
#include <cstdint>

#define BB 64
#define NP 1024
#define LL 64
#define HH 128
#define W1K 67
#define TN 128
#define NT (BB * 8)       // 512 tiles of 128 points
#define MLP_GRID 148
#define KS 136            // bf16 elements per row (272B, 16B-aligned stride)
#define H2ROW 132         // fp32 row stride for h2

__device__ float g_acc[3];
__device__ float g_w1l[BB * HH];

__global__ void init_kernel() {
    if (threadIdx.x < 3) g_acc[threadIdx.x] = 0.0f;
}

__global__ void __launch_bounds__(128) w1l_kernel(
    const float* __restrict__ latent, const float* __restrict__ W1,
    const float* __restrict__ b1)
{
    __shared__ float slat[LL];
    const int b = blockIdx.x, o = threadIdx.x;
    if (o < LL) slat[o] = latent[b * LL + o];
    __syncthreads();
    float acc = b1[o];
    const float* wrow = W1 + o * W1K + 3;
    #pragma unroll 8
    for (int l = 0; l < LL; l++) acc = fmaf(wrow[l], slat[l], acc);
    g_w1l[b * HH + o] = acc;
}

__device__ __forceinline__ float block_sum(float v, float* scratch) {
    #pragma unroll
    for (int off = 16; off; off >>= 1) v += __shfl_down_sync(0xffffffffu, v, off);
    int lane = threadIdx.x & 31, w = threadIdx.x >> 5;
    if (lane == 0) scratch[w] = v;
    __syncthreads();
    int nw = blockDim.x >> 5;
    v = (threadIdx.x < nw) ? scratch[threadIdx.x] : 0.0f;
    if (w == 0) {
        #pragma unroll
        for (int off = 16; off; off >>= 1) v += __shfl_down_sync(0xffffffffu, v, off);
    }
    return v;
}

__device__ __forceinline__ uint32_t smem_u32(const void* p) {
    uint32_t a;
    asm("{ .reg .u64 t; cvta.to.shared.u64 t, %1; cvt.u32.u64 %0, t; }"
        : "=r"(a) : "l"(p));
    return a;
}
__device__ __forceinline__ void ldmx4(uint32_t* r, uint32_t addr) {
    asm volatile("ldmatrix.sync.aligned.m8n8.x4.shared.b16 {%0,%1,%2,%3}, [%4];"
                 : "=r"(r[0]), "=r"(r[1]), "=r"(r[2]), "=r"(r[3]) : "r"(addr));
}
__device__ __forceinline__ void ldmx2(uint32_t* r, uint32_t addr) {
    asm volatile("ldmatrix.sync.aligned.m8n8.x2.shared.b16 {%0,%1}, [%2];"
                 : "=r"(r[0]), "=r"(r[1]) : "r"(addr));
}
__device__ __forceinline__ void mma_bf16(float* c, const uint32_t* a,
                                         const uint32_t* b) {
    asm volatile(
        "mma.sync.aligned.m16n8k16.row.col.f32.bf16.bf16.f32 "
        "{%0,%1,%2,%3}, {%4,%5,%6,%7}, {%8,%9}, {%0,%1,%2,%3};"
        : "+f"(c[0]), "+f"(c[1]), "+f"(c[2]), "+f"(c[3])
        : "r"(a[0]), "r"(a[1]), "r"(a[2]), "r"(a[3]), "r"(b[0]), "r"(b[1]));
}
__device__ __forceinline__ unsigned pack_bf2(__nv_bfloat16 a, __nv_bfloat16 b) {
    return (unsigned)__bfloat16_as_ushort(a) |
           ((unsigned)__bfloat16_as_ushort(b) << 16);
}

// SMEM byte offsets within dynamic region
#define OFF_W2HI 0
#define OFF_W2LO 34816
#define OFF_HHI  69632
#define OFF_HLO  104448
#define OFF_H2   69632          // overlays HHI/HLO (read-after-mma only)
#define OFF_MISC 139264

// ---------------------------------------------------------------------------
// Persistent MLP, split-bf16 mma.sync GEMM2. 148 CTAs x 256 thr, 512 tiles.
// ---------------------------------------------------------------------------
__global__ void __launch_bounds__(256) mlp_kernel(
    const float* __restrict__ pc, const float* __restrict__ pc_gt,
    const float* __restrict__ W2, const float* __restrict__ b2,
    const float* __restrict__ W1,
    const float* __restrict__ W3, const float* __restrict__ b3,
    float* __restrict__ out_est)
{
    extern __shared__ float smf[];
    char* sb = (char*)smf;
    __nv_bfloat16* w2hi = (__nv_bfloat16*)(sb + OFF_W2HI);  // [o][KS]
    __nv_bfloat16* w2lo = (__nv_bfloat16*)(sb + OFF_W2LO);
    __nv_bfloat16* hhi  = (__nv_bfloat16*)(sb + OFF_HHI);   // [n][KS]
    __nv_bfloat16* hlo  = (__nv_bfloat16*)(sb + OFF_HLO);
    float* s_h2 = (float*)(sb + OFF_H2);                    // [128][H2ROW]
    float* misc = (float*)(sb + OFF_MISC);
    float* swx  = misc;           // [3][128]
    float* swl  = swx + 384;      // 128
    float* sb2  = swl + 128;      // 128
    float* sw3  = sb2 + 128;      // 384
    float* sb3  = sw3 + 384;      // 4
    float* s_x  = sb3 + 4;        // [3][128]
    float* sred = s_x + 384;      // 8

    const int tid = threadIdx.x;
    const int lane = tid & 31;
    const int wid = tid >> 5;

    // ---- one-time stage: W2 hi/lo (bf16 split), small weights ----
    {
        const int o = tid & 127, kh = tid >> 7;
        const float* w2r = W2 + o * HH;
        for (int k = kh * 64; k < kh * 64 + 64; k += 2) {
            float w0 = w2r[k], w1 = w2r[k + 1];
            __nv_bfloat16 h0 = __float2bfloat16(w0);
            __nv_bfloat16 h1 = __float2bfloat16(w1);
            *(unsigned*)&w2hi[o * KS + k] = pack_bf2(h0, h1);
            *(unsigned*)&w2lo[o * KS + k] =
                pack_bf2(__float2bfloat16(w0 - __bfloat162float(h0)),
                         __float2bfloat16(w1 - __bfloat162float(h1)));
        }
    }
    for (int i = tid; i < 384; i += 256) {
        int k = i >> 7, o = i & 127;
        swx[k * 128 + o] = W1[o * W1K + k];
        sw3[i] = W3[i];
    }
    if (tid < 128) sb2[tid] = b2[tid];
    if (tid < 3) sb3[tid] = b3[tid];
    __syncthreads();

    const uint32_t u_w2hi = smem_u32(w2hi);
    const uint32_t u_w2lo = smem_u32(w2lo);
    const uint32_t u_hhi  = smem_u32(hhi);
    const uint32_t u_hlo  = smem_u32(hlo);

    // ldmatrix lane-address components
    const int lr = lane & 7;
    const int aq = lane >> 3;                 // A quadrant 0..3
    const int arow_off = ((aq & 1) << 3) + lr;
    const int acol_off = (aq >> 1) << 3;
    const int bl15 = lane & 15;
    const int brow_off = bl15 & 7;
    const int bcol_off = (bl15 >> 3) << 3;

    const int o0 = wid * 16;
    float l2acc = 0.0f;

    for (int t = blockIdx.x; t < NT; t += MLP_GRID) {
        const int b  = t >> 3;
        const int n0 = (t & 7) * TN;

        __syncthreads();   // prior tile layer-3 reads of s_h2 done
        for (int i = tid; i < 384; i += 256) {
            int k = i >> 7, n = i & 127;
            s_x[k * 128 + n] = pc[(b * 3 + k) * NP + n0 + n];
        }
        if (tid < 128) swl[tid] = g_w1l[b * HH + tid];
        __syncthreads();

        // ---- layer 1 (fp32) -> split-bf16 h tiles [n][k] ----
        {
            const int n = tid & 127, kh = tid >> 7;
            const float x0 = s_x[n], x1 = s_x[128 + n], x2 = s_x[256 + n];
            #pragma unroll
            for (int k = kh * 64; k < kh * 64 + 64; k += 2) {
                float h0 = fmaxf(fmaf(swx[k], x0, fmaf(swx[128 + k], x1,
                             fmaf(swx[256 + k], x2, swl[k]))), 0.0f);
                float h1v = fmaxf(fmaf(swx[k + 1], x0, fmaf(swx[129 + k], x1,
                              fmaf(swx[257 + k], x2, swl[k + 1]))), 0.0f);
                __nv_bfloat16 bh0 = __float2bfloat16(h0);
                __nv_bfloat16 bh1 = __float2bfloat16(h1v);
                *(unsigned*)&hhi[n * KS + k] = pack_bf2(bh0, bh1);
                *(unsigned*)&hlo[n * KS + k] =
                    pack_bf2(__float2bfloat16(h0 - __bfloat162float(bh0)),
                             __float2bfloat16(h1v - __bfloat162float(bh1)));
            }
        }
        __syncthreads();

        // ---- GEMM2: warp o-strip [o0,o0+16), split-bf16 mma.sync ----
        float C[16][4];
        #pragma unroll
        for (int nt = 0; nt < 16; nt++)
            #pragma unroll
            for (int j = 0; j < 4; j++) C[nt][j] = 0.0f;

        #pragma unroll
        for (int k8 = 0; k8 < 8; k8++) {
            const int k0 = k8 * 16;
            const uint32_t aoff = (uint32_t)(o0 + arow_off) * 272u +
                                  (uint32_t)(k0 + acol_off) * 2u;
            uint32_t ah[4], al[4];
            ldmx4(ah, u_w2hi + aoff);
            ldmx4(al, u_w2lo + aoff);
            #pragma unroll
            for (int nt = 0; nt < 16; nt++) {
                const uint32_t boff = (uint32_t)(nt * 8 + brow_off) * 272u +
                                      (uint32_t)(k0 + bcol_off) * 2u;
                uint32_t bh[2], bl[2];
                ldmx2(bh, u_hhi + boff);
                ldmx2(bl, u_hlo + boff);
                mma_bf16(C[nt], ah, bh);
                mma_bf16(C[nt], ah, bl);
                mma_bf16(C[nt], al, bh);
            }
        }
        __syncthreads();   // all warps done reading h before s_h2 overlay

        // ---- bias + relu -> s_h2[o][n] ----
        {
            const int r = lane >> 2;
            const int cp = (lane & 3) * 2;
            const float bo  = sb2[o0 + r];
            const float bo8 = sb2[o0 + r + 8];
            #pragma unroll
            for (int nt = 0; nt < 16; nt++) {
                int n = nt * 8 + cp;
                s_h2[(o0 + r) * H2ROW + n]     = fmaxf(C[nt][0] + bo, 0.0f);
                s_h2[(o0 + r) * H2ROW + n + 1] = fmaxf(C[nt][1] + bo, 0.0f);
                s_h2[(o0 + r + 8) * H2ROW + n]     = fmaxf(C[nt][2] + bo8, 0.0f);
                s_h2[(o0 + r + 8) * H2ROW + n + 1] = fmaxf(C[nt][3] + bo8, 0.0f);
            }
        }
        __syncthreads();

        // ---- layer 3 (fp32, 3x128) + epilogue (R8-proven) ----
        if (tid < TN) {
            int n = tid, g = n0 + n;
            float o0v = sb3[0], o1v = sb3[1], o2v = sb3[2];
            #pragma unroll 4
            for (int k = 0; k < HH; k++) {
                float hv = s_h2[k * H2ROW + n];
                o0v = fmaf(sw3[k], hv, o0v);
                o1v = fmaf(sw3[128 + k], hv, o1v);
                o2v = fmaf(sw3[256 + k], hv, o2v);
            }
            int base = (b * 3) * NP + g;
            float e0 = pc[base] - o0v;
            float e1 = pc[base + NP] - o1v;
            float e2 = pc[base + 2 * NP] - o2v;
            out_est[base] = e0;
            out_est[base + NP] = e1;
            out_est[base + 2 * NP] = e2;
            float d0 = pc_gt[base] - e0;
            float d1 = pc_gt[base + NP] - e1;
            float d2 = pc_gt[base + 2 * NP] - e2;
            l2acc += fmaf(d0, d0, fmaf(d1, d1, d2 * d2));
        }
    }

    __syncthreads();
    float s = block_sum(l2acc, sred);
    if (tid == 0) atomicAdd(&g_acc[2], s);
}

// ---------------------------------------------------------------------------
// Chamfer (unchanged from R8): 512 thr, 4 queries/thread, split m-scan.
// ---------------------------------------------------------------------------
__global__ void __launch_bounds__(512) chamfer_kernel(
    const float* __restrict__ pc_gt, const float* __restrict__ est)
{
    __shared__ float4 spts[NP];
    __shared__ float sup[256][4];
    __shared__ float sred[16];
    const int b = blockIdx.x;
    const int dir = blockIdx.y;
    const float* rows  = dir ? est   : pc_gt;
    const float* other = dir ? pc_gt : est;
    const int base = b * 3 * NP;
    const int tid  = threadIdx.x;
    const int qt   = tid & 255;
    const int half = tid >> 8;

    for (int i = tid; i < NP; i += 512) {
        float x = other[base + i];
        float y = other[base + NP + i];
        float z = other[base + 2 * NP + i];
        spts[i] = make_float4(x, y, z, fmaf(x, x, fmaf(y, y, z * z)));
    }
    __syncthreads();

    float qx[4], qy[4], qz[4], qa2[4];
    #pragma unroll
    for (int q = 0; q < 4; q++) {
        int n = qt + q * 256;
        float ax = rows[base + n];
        float ay = rows[base + NP + n];
        float az = rows[base + 2 * NP + n];
        qa2[q] = fmaf(ax, ax, fmaf(ay, ay, az * az));
        qx[q] = -2.0f * ax;
        qy[q] = -2.0f * ay;
        qz[q] = -2.0f * az;
    }

    float bst[4][2];
    #pragma unroll
    for (int q = 0; q < 4; q++) { bst[q][0] = 3.4e38f; bst[q][1] = 3.4e38f; }

    const int m0 = half * 512;
    for (int m = m0; m < m0 + 512; m += 4) {
        float4 p0 = spts[m];
        float4 p1 = spts[m + 1];
        float4 p2 = spts[m + 2];
        float4 p3 = spts[m + 3];
        #pragma unroll
        for (int q = 0; q < 4; q++) {
            float t0 = fmaf(qz[q], p0.z, fmaf(qy[q], p0.y, fmaf(qx[q], p0.x, p0.w)));
            float t1 = fmaf(qz[q], p1.z, fmaf(qy[q], p1.y, fmaf(qx[q], p1.x, p1.w)));
            float t2 = fmaf(qz[q], p2.z, fmaf(qy[q], p2.y, fmaf(qx[q], p2.x, p2.w)));
            float t3 = fmaf(qz[q], p3.z, fmaf(qy[q], p3.y, fmaf(qx[q], p3.x, p3.w)));
            bst[q][0] = fminf(bst[q][0], fminf(t0, t1));
            bst[q][1] = fminf(bst[q][1], fminf(t2, t3));
        }
    }

    if (half) {
        #pragma unroll
        for (int q = 0; q < 4; q++)
            sup[qt][q] = fminf(bst[q][0], bst[q][1]);
    }
    __syncthreads();

    float acc = 0.0f;
    if (!half) {
        #pragma unroll
        for (int q = 0; q < 4; q++) {
            float lo = fminf(bst[q][0], bst[q][1]);
            acc += qa2[q] + fminf(lo, sup[qt][q]);
        }
    }
    float s = block_sum(acc, sred);
    if (tid == 0) atomicAdd(&g_acc[dir], s);
}

__global__ void final_kernel(float* __restrict__ out) {
    float ch = (g_acc[0] + g_acc[1]) * (1.0f / (float)(BB * NP));
    float l2 = g_acc[2] * (1.0f / (float)(BB * 3 * NP));
    out[0] = 0.1f * ch + 0.9f * l2;
    out[1] = ch;
    out[2] = l2;
}

extern "C" void kernel_launch(void* const* d_in, const int* in_sizes, int n_in,
                              void* d_out, int out_size) {
    const float* pc    = (const float*)d_in[0];
    const float* pc_gt = (const float*)d_in[1];
    const float* lat   = (const float*)d_in[2];
    const float* W1    = (const float*)d_in[3];
    const float* b1    = (const float*)d_in[4];
    const float* W2    = (const float*)d_in[5];
    const float* b2    = (const float*)d_in[6];
    const float* W3    = (const float*)d_in[7];
    const float* b3    = (const float*)d_in[8];
    float* out = (float*)d_out;

    size_t smem = OFF_MISC + (size_t)(384 + 128 + 128 + 384 + 4 + 384 + 16)
                             * sizeof(float);
    (void)cudaFuncSetAttribute(mlp_kernel,
                               cudaFuncAttributeMaxDynamicSharedMemorySize,
                               (int)smem);

    init_kernel<<<1, 32>>>();
    w1l_kernel<<<BB, 128>>>(lat, W1, b1);
    mlp_kernel<<<MLP_GRID, 256, smem>>>(pc, pc_gt, W2, b2, W1, W3, b3, out + 3);
    chamfer_kernel<<<dim3(BB, 2), 512>>>(pc_gt, out + 3);
    final_kernel<<<1, 1>>>(out);
}